// round 17
// baseline (speedup 1.0000x reference)
#include <cuda_runtime.h>
#include <cuda_fp16.h>
#include <math.h>
#include <stdint.h>

// ---------------------------------------------------------------------------
// Problem constants
// ---------------------------------------------------------------------------
constexpr int BATCH = 8;
constexpr int SQ    = 2048;
constexpr int SKV   = 2048;
constexpr int DIN   = 1024;
constexpr int DEMB  = 512;
constexpr int DOUT  = 512;

constexpr long PROJ_ELEMS = (long)BATCH * SQ * DOUT;

// ---------------------------------------------------------------------------
// Scratch (device globals; no allocation allowed)
// ---------------------------------------------------------------------------
__device__ __align__(16) uint16_t g_xh  [(long)BATCH * SQ * DIN];    // fp16
__device__ __align__(16) uint16_t g_wqT [DEMB * DIN];                // fp16
__device__ __align__(16) uint16_t g_enS [(long)BATCH * SKV * DEMB];  // fp16, K-major
__device__ __align__(16) uint16_t g_enT [(long)BATCH * DEMB * SKV];  // fp16, transposed
__device__ __align__(16) uint16_t g_wfT [DOUT * DEMB];               // fp16
__device__ __align__(16) float    g_q   [(long)BATCH * SQ * DEMB];   // fp32 (residual)
__device__ __align__(16) uint16_t g_qh  [(long)BATCH * SQ * DEMB];   // fp16 single
__device__ __align__(16) uint16_t g_attH[(long)BATCH * SQ * SKV];    // fp16 att (post-softmax)
__device__ __align__(16) uint16_t g_sumh[(long)BATCH * SQ * DEMB];   // fp16 sum

// ---------------------------------------------------------------------------
// PTX helpers (sm_80-compatible path: mma.sync / ldmatrix / cp.async)
// ---------------------------------------------------------------------------
__device__ __forceinline__ uint32_t smem_u32(const void* p) {
    uint32_t a;
    asm("{ .reg .u64 t; cvta.to.shared.u64 t, %1; cvt.u32.u64 %0, t; }" : "=r"(a) : "l"(p));
    return a;
}

#define CP_ASYNC16(dst, src) \
    asm volatile("cp.async.cg.shared.global [%0], [%1], 16;" :: "r"(dst), "l"(src))
#define CP_COMMIT()  asm volatile("cp.async.commit_group;" ::: "memory")
#define CP_WAIT0()   asm volatile("cp.async.wait_group 0;" ::: "memory")
#define CP_WAIT1()   asm volatile("cp.async.wait_group 1;" ::: "memory")
#define CP_WAIT2()   asm volatile("cp.async.wait_group 2;" ::: "memory")

#define LDSM_X4(r0, r1, r2, r3, addr) \
    asm volatile("ldmatrix.sync.aligned.m8n8.x4.shared.b16 {%0,%1,%2,%3}, [%4];" \
                 : "=r"(r0), "=r"(r1), "=r"(r2), "=r"(r3) : "r"(addr))

__device__ __forceinline__ void mma_h(float* d, const uint32_t* a, uint32_t b0, uint32_t b1) {
    asm volatile("mma.sync.aligned.m16n8k16.row.col.f32.f16.f16.f32 "
                 "{%0,%1,%2,%3}, {%4,%5,%6,%7}, {%8,%9}, {%0,%1,%2,%3};"
                 : "+f"(d[0]), "+f"(d[1]), "+f"(d[2]), "+f"(d[3])
                 : "r"(a[0]), "r"(a[1]), "r"(a[2]), "r"(a[3]), "r"(b0), "r"(b1));
}

// ---------------------------------------------------------------------------
// helpers
// ---------------------------------------------------------------------------
__device__ __forceinline__ uint32_t pk(uint16_t a, uint16_t b) {
    return (uint32_t)a | ((uint32_t)b << 16);
}
__device__ __forceinline__ uint16_t h16(float v) {
    return __half_as_ushort(__float2half_rn(v));
}

// ---------------------------------------------------------------------------
// Pre-pass kernels
// ---------------------------------------------------------------------------
// plain fp32 -> fp16 convert
__global__ void __launch_bounds__(256)
conv_plain_f16(const float* __restrict__ src, uint16_t* __restrict__ dst, long n4)
{
    long i = (long)blockIdx.x * 256 + threadIdx.x;
    if (i >= n4) return;
    float4 v = reinterpret_cast<const float4*>(src)[i];
    reinterpret_cast<uint2*>(dst)[i] =
        make_uint2(pk(h16(v.x), h16(v.y)), pk(h16(v.z), h16(v.w)));
}

// en -> fp16 single (same layout) + fp16 single transposed [DEMB, SKV]
__global__ void __launch_bounds__(256)
conv_en_fused(const float* __restrict__ en, uint16_t* __restrict__ eS,
              uint16_t* __restrict__ eT)
{
    const long z = blockIdx.z;
    en += z * (long)SKV * DEMB;
    eS += z * (long)SKV * DEMB;
    eT += z * (long)DEMB * SKV;
    __shared__ float t[32][33];
    const int c0 = blockIdx.x * 32;   // DEMB
    const int r0 = blockIdx.y * 32;   // SKV
    const int tx = threadIdx.x, ty = threadIdx.y;
#pragma unroll
    for (int j = 0; j < 4; j++) {
        int r = r0 + ty + j * 8;
        float v = en[(long)r * DEMB + c0 + tx];
        t[ty + j * 8][tx] = v;
        eS[(long)r * DEMB + c0 + tx] = h16(v);
    }
    __syncthreads();
#pragma unroll
    for (int j = 0; j < 4; j++) {
        int c = c0 + ty + j * 8;
        eT[(long)c * SKV + r0 + tx] = h16(t[tx][ty + j * 8]);
    }
}

// W [R,C] fp32 -> WT [C,R] fp16 single
__global__ void __launch_bounds__(256)
conv_T_f16(const float* __restrict__ src, uint16_t* __restrict__ dstT, int R, int C)
{
    __shared__ float t[32][33];
    const int c0 = blockIdx.x * 32;
    const int r0 = blockIdx.y * 32;
    const int tx = threadIdx.x, ty = threadIdx.y;
#pragma unroll
    for (int j = 0; j < 4; j++) {
        int r = r0 + ty + j * 8;
        t[ty + j * 8][tx] = src[(long)r * C + c0 + tx];
    }
    __syncthreads();
#pragma unroll
    for (int j = 0; j < 4; j++) {
        int c = c0 + ty + j * 8;
        dstT[(long)c * R + r0 + tx] = h16(t[tx][ty + j * 8]);
    }
}

// ---------------------------------------------------------------------------
// fp16 HMMA GEMM: C[M,N] = A[M,K] @ B[N,K]^T (+epilogue)
// 1-pass fp16, 3-stage cp.async pipeline, 2 SMEM tiles per stage,
// 4 warps of 64x64 (CTA tile 128x128), mma.sync m16n8k16.
// MODE bits: 1=bias, 2=scale, 4=residual, 8=write fp32, 16=write fp16 single
// ---------------------------------------------------------------------------
constexpr int ROWB  = 80;             // padded row bytes (32 elems * 2B = 64B data)
constexpr int TILEB = 128 * ROWB;     // 10240 B
constexpr int STAGES = 3;
constexpr int SMEM_BYTES = STAGES * 2 * TILEB;  // 61440
constexpr int GTHREADS = 128;         // 4 warps

template <int MODE>
__global__ void __launch_bounds__(GTHREADS, 2)
mma_gemm(const uint16_t* __restrict__ Ah, const uint16_t* __restrict__ Bs,
         float* __restrict__ Cf, uint16_t* __restrict__ Ch,
         const float* __restrict__ aux,
         int M, int N, int K, long sA, long sB, long sC, long sAux, float scale)
{
    constexpr bool HAS_BIAS  = (MODE & 1)  != 0;
    constexpr bool HAS_SCALE = (MODE & 2)  != 0;
    constexpr bool HAS_RES   = (MODE & 4)  != 0;
    constexpr bool WR_F32    = (MODE & 8)  != 0;
    constexpr bool WR_F16    = (MODE & 16) != 0;

    extern __shared__ __align__(128) char dsm[];
    const uint32_t sbase = smem_u32(dsm);
    #define TILE(s, t) (sbase + ((s) * 2 + (t)) * TILEB)

    const int tid  = threadIdx.x;
    const int wid  = tid >> 5;
    const int lane = tid & 31;

    const long z = blockIdx.z;
    Ah += z * sA;
    Bs += z * sB;
    const long cOff = z * sC;

    const int m0 = blockIdx.y * 128;
    const int n0 = blockIdx.x * 128;

    const int lrow = tid >> 2;           // 0..31
    const int lkg  = tid & 3;            // 16B group
    auto load_chunk = [&](int s, int k0) {
        {
            const uint16_t* g = Ah + (long)m0 * K + k0;
            const uint32_t st = TILE(s, 0);
#pragma unroll
            for (int h = 0; h < 4; h++) {
                int row = lrow + h * 32;
                CP_ASYNC16(st + row * ROWB + lkg * 16, g + (long)row * K + lkg * 8);
            }
        }
        {
            const uint16_t* g = Bs + (long)n0 * K + k0;
            const uint32_t st = TILE(s, 1);
#pragma unroll
            for (int h = 0; h < 4; h++) {
                int row = lrow + h * 32;
                CP_ASYNC16(st + row * ROWB + lkg * 16, g + (long)row * K + lkg * 8);
            }
        }
    };

    float acc[4][8][4];
#pragma unroll
    for (int a = 0; a < 4; a++)
#pragma unroll
        for (int b = 0; b < 8; b++)
#pragma unroll
            for (int c = 0; c < 4; c++) acc[a][b][c] = 0.0f;

    const int nch = K >> 5;

    // prologue: 2 chunk-loads in flight
    load_chunk(0, 0);
    CP_COMMIT();
    if (nch > 1) {
        load_chunk(1, 32);
        CP_COMMIT();
    }

    // warp layout: 2 (m) x 2 (n); warp tile 64x64
    const int m0w = (wid & 1) * 64;
    const int n0w = (wid >> 1) * 64;
    const int a_r = lane & 15;
    const int a_h = lane >> 4;
    const int b_r = lane & 7;
    const int b_q = lane >> 3;

    for (int i = 0; i < nch; i++) {
        // issue load for chunk i+2 (stage reuse protected by the trailing
        // __syncthreads of iteration i-1)
        if (i + 2 < nch) {
            load_chunk((i + 2) % STAGES, (i + 2) * 32);
            CP_COMMIT();
        }
        // wait until chunk i has landed
        if (i + 2 < nch)      CP_WAIT2();
        else if (i + 1 < nch) CP_WAIT1();
        else                  CP_WAIT0();
        __syncthreads();

        const int s = i % STAGES;
        const uint32_t Ab = TILE(s, 0);
        const uint32_t Bb = TILE(s, 1);

#pragma unroll
        for (int ks = 0; ks < 2; ks++) {
            const int koff = ks * 32;
            uint32_t bh[16];
#pragma unroll
            for (int j = 0; j < 4; j++) {
                uint32_t boff = (uint32_t)((n0w + j * 16 + (b_q >> 1) * 8 + b_r) * ROWB
                                           + koff + (b_q & 1) * 16);
                LDSM_X4(bh[j*4+0], bh[j*4+1], bh[j*4+2], bh[j*4+3], Bb + boff);
            }
#pragma unroll
            for (int mi = 0; mi < 4; mi++) {
                uint32_t aoff = (uint32_t)((m0w + mi * 16 + a_r) * ROWB + koff + a_h * 16);
                uint32_t ahr[4];
                LDSM_X4(ahr[0], ahr[1], ahr[2], ahr[3], Ab + aoff);
#pragma unroll
                for (int ni = 0; ni < 8; ni++)
                    mma_h(acc[mi][ni], ahr, bh[ni*2], bh[ni*2+1]);
            }
        }
        __syncthreads();
    }

    // ---- epilogue ----
    const float* auxp = aux;
    if (HAS_RES) auxp += z * sAux;
    const int crow = lane >> 2;
    const int ccol = (lane & 3) * 2;
#pragma unroll
    for (int mi = 0; mi < 4; mi++) {
#pragma unroll
        for (int rh = 0; rh < 2; rh++) {
            const long row = m0 + m0w + mi * 16 + crow + rh * 8;
#pragma unroll
            for (int ni = 0; ni < 8; ni++) {
                const int col = n0 + n0w + ni * 8 + ccol;
                float v0 = acc[mi][ni][rh * 2];
                float v1 = acc[mi][ni][rh * 2 + 1];
                if (HAS_BIAS)  { v0 += aux[col]; v1 += aux[col + 1]; }
                if (HAS_SCALE) { v0 *= scale; v1 *= scale; }
                if (HAS_RES)   {
                    v0 += auxp[row * (long)N + col];
                    v1 += auxp[row * (long)N + col + 1];
                }
                if (WR_F32)
                    *reinterpret_cast<float2*>(Cf + cOff + row * (long)N + col) =
                        make_float2(v0, v1);
                if (WR_F16)
                    *reinterpret_cast<uint32_t*>(Ch + cOff + row * (long)N + col) =
                        pk(h16(v0), h16(v1));
            }
        }
    }
    #undef TILE
}

// ---------------------------------------------------------------------------
// In-place fp32 row softmax over 2048 columns + fp16 copy for the A*V GEMM.
// ---------------------------------------------------------------------------
__global__ void __launch_bounds__(256)
softmax_rows(float* __restrict__ att, uint16_t* __restrict__ attH)
{
    const long row = blockIdx.x;
    float* p = att + row * (long)SKV;
    uint16_t* ph = attH + row * (long)SKV;
    const int t = threadIdx.x;
    const int w = t >> 5, ln = t & 31;
    __shared__ float red[8];

    float v[8];
    float m = -INFINITY;
#pragma unroll
    for (int i = 0; i < 8; i++) {
        v[i] = p[t + i * 256];
        m = fmaxf(m, v[i]);
    }
#pragma unroll
    for (int s = 16; s > 0; s >>= 1)
        m = fmaxf(m, __shfl_xor_sync(0xFFFFFFFFu, m, s));
    if (ln == 0) red[w] = m;
    __syncthreads();
    m = red[ln & 7];
#pragma unroll
    for (int s = 4; s > 0; s >>= 1)
        m = fmaxf(m, __shfl_xor_sync(0xFFFFFFFFu, m, s));

    float sum = 0.0f;
#pragma unroll
    for (int i = 0; i < 8; i++) {
        v[i] = __expf(v[i] - m);
        sum += v[i];
    }
#pragma unroll
    for (int s = 16; s > 0; s >>= 1)
        sum += __shfl_xor_sync(0xFFFFFFFFu, sum, s);
    __syncthreads();
    if (ln == 0) red[w] = sum;
    __syncthreads();
    sum = red[ln & 7];
#pragma unroll
    for (int s = 4; s > 0; s >>= 1)
        sum += __shfl_xor_sync(0xFFFFFFFFu, sum, s);

    const float inv = 1.0f / sum;
#pragma unroll
    for (int i = 0; i < 8; i++) {
        float val = v[i] * inv;
        p[t + i * 256] = val;
        ph[t + i * 256] = h16(val);
    }
}

// ---------------------------------------------------------------------------
extern "C" void kernel_launch(void* const* d_in, const int* in_sizes, int n_in,
                              void* d_out, int out_size)
{
    const float* x  = (const float*)d_in[0];
    const float* en = (const float*)d_in[1];
    const float* Wq = (const float*)d_in[2];
    const float* bq = (const float*)d_in[3];
    const float* Wf = (const float*)d_in[4];
    const float* bf = (const float*)d_in[5];

    float* out  = (float*)d_out;
    float* proj = out;
    float* att  = out + PROJ_ELEMS;

    auto sym = [](const void* s) {
        void* p = nullptr;
        cudaGetSymbolAddress(&p, s);
        return p;
    };
    uint16_t* xh   = (uint16_t*)sym(g_xh);
    uint16_t* wqT  = (uint16_t*)sym(g_wqT);
    uint16_t* enS  = (uint16_t*)sym(g_enS);
    uint16_t* enT  = (uint16_t*)sym(g_enT);
    uint16_t* wfT  = (uint16_t*)sym(g_wfT);
    float*    qf   = (float*)   sym(g_q);
    uint16_t* qh   = (uint16_t*)sym(g_qh);
    uint16_t* attH = (uint16_t*)sym(g_attH);
    uint16_t* sumh = (uint16_t*)sym(g_sumh);

    cudaFuncSetAttribute(mma_gemm<25>, cudaFuncAttributeMaxDynamicSharedMemorySize, SMEM_BYTES);
    cudaFuncSetAttribute(mma_gemm<10>, cudaFuncAttributeMaxDynamicSharedMemorySize, SMEM_BYTES);
    cudaFuncSetAttribute(mma_gemm<20>, cudaFuncAttributeMaxDynamicSharedMemorySize, SMEM_BYTES);
    cudaFuncSetAttribute(mma_gemm<9>,  cudaFuncAttributeMaxDynamicSharedMemorySize, SMEM_BYTES);

    const float scale = 0.044194173824159216f;  // 1/sqrt(512)

    // --- pre-passes ---
    {
        long n4 = (long)BATCH * SQ * DIN / 4;
        conv_plain_f16<<<(unsigned)((n4 + 255) / 256), 256>>>(x, xh, n4);
    }
    conv_en_fused<<<dim3(DEMB / 32, SKV / 32, BATCH), dim3(32, 8)>>>(en, enS, enT);
    conv_T_f16<<<dim3(DEMB / 32, DIN / 32, 1), dim3(32, 8)>>>(Wq, wqT, DIN, DEMB);
    conv_T_f16<<<dim3(DOUT / 32, DEMB / 32, 1), dim3(32, 8)>>>(Wf, wfT, DEMB, DOUT);

    // 1) q = x @ wqT^T + bq    writes q fp32 + fp16 single. MODE=1|8|16=25
    mma_gemm<25><<<dim3(DEMB / 128, (BATCH * SQ) / 128, 1), GTHREADS, SMEM_BYTES>>>(
        xh, wqT, qf, qh, bq,
        BATCH * SQ, DEMB, DIN, 0, 0, 0, 0, 0.0f);

    // 2) scores = q @ enS^T * scale    fp32 att. MODE=2|8=10
    mma_gemm<10><<<dim3(SKV / 128, SQ / 128, BATCH), GTHREADS, SMEM_BYTES>>>(
        qh, enS, att, nullptr, nullptr,
        SQ, SKV, DEMB,
        (long)SQ * DEMB, (long)SKV * DEMB, (long)SQ * SKV, 0, scale);

    // 3) softmax in-place fp32 + fp16 copy
    softmax_rows<<<BATCH * SQ, 256>>>(att, attH);

    // 4) sum = attH @ enT^T + q    fp16 sum out. MODE=4|16=20
    mma_gemm<20><<<dim3(DEMB / 128, SQ / 128, BATCH), GTHREADS, SMEM_BYTES>>>(
        attH, enT, nullptr, sumh, qf,
        SQ, DEMB, SKV,
        (long)SQ * SKV, (long)DEMB * SKV, (long)SQ * DEMB, (long)SQ * DEMB, 0.0f);

    // 5) proj = sumh @ wfT^T + bf    fp32 out. MODE=1|8=9
    mma_gemm<9><<<dim3(DOUT / 128, (BATCH * SQ) / 128, 1), GTHREADS, SMEM_BYTES>>>(
        sumh, wfT, proj, nullptr, bf,
        BATCH * SQ, DOUT, DEMB, 0, 0, 0, 0, 0.0f);

    (void)in_sizes; (void)n_in; (void)out_size;
}